// round 5
// baseline (speedup 1.0000x reference)
#include <cuda_runtime.h>
#include <cuda_fp16.h>
#include <cstdint>

#define M_DIM 8192
#define K_DIM 4096
#define N_DIM 11008
#define NG_DIM 32

#define TILE_M 128
#define TILE_N 128
#define NT (N_DIM / TILE_N) /* 86 */
#define MT (M_DIM / TILE_M) /* 64 */
#define NTHREADS 512

// ---------------- scratch (static device arrays: allocation-free) ----------------
__device__ __half g_xhi[(size_t)M_DIM * K_DIM];
__device__ float  g_S[NG_DIM * M_DIM];   // S[g*M + m] = sum over group g of fp16-rounded x

// ---------------- smem layout: two buffers ----------------
// per buffer: A 32KB | B 32KB | Wpacked 8KB | scales 512B | zeros 512B
#define B_A  0
#define B_B  32768
#define B_W  65536
#define B_SZ 73728
#define BUF_STRIDE 74752
#define SMEM_BYTES (2 * BUF_STRIDE) /* 149504 */

// ---------------- helpers ----------------
__device__ __forceinline__ uint32_t smem_u32(const void* p) {
    uint32_t a;
    asm("{ .reg .u64 t; cvta.to.shared.u64 t, %1; cvt.u32.u64 %0, t; }" : "=r"(a) : "l"(p));
    return a;
}

#define CP_ASYNC16(dst, src) \
    asm volatile("cp.async.cg.shared.global [%0], [%1], 16;" :: "r"(dst), "l"(src))
#define CP_COMMIT() asm volatile("cp.async.commit_group;" ::: "memory")
#define CP_WAIT0()  asm volatile("cp.async.wait_group 0;" ::: "memory")

#define LDSM_X4(r0, r1, r2, r3, addr) \
    asm volatile("ldmatrix.sync.aligned.m8n8.x4.shared.b16 {%0,%1,%2,%3}, [%4];" \
                 : "=r"(r0), "=r"(r1), "=r"(r2), "=r"(r3) : "r"(addr))

#define MMA16816(d, a, b0v, b1v) \
    asm volatile("mma.sync.aligned.m16n8k16.row.col.f32.f16.f16.f32 " \
                 "{%0,%1,%2,%3}, {%4,%5,%6,%7}, {%8,%9}, {%0,%1,%2,%3};" \
                 : "+f"((d)[0]), "+f"((d)[1]), "+f"((d)[2]), "+f"((d)[3]) \
                 : "r"((a)[0]), "r"((a)[1]), "r"((a)[2]), "r"((a)[3]), \
                   "r"(b0v), "r"(b1v))

// one packed int32 word -> 8 exact fp16 nibble values, K-ascending, as 4 u32
__device__ __forceinline__ void dequant8(uint32_t w, uint32_t r[4]) {
    const uint32_t MASK = 0x000F000Fu, BIAS = 0x64006400u;
    uint32_t q0 = ((w      ) & MASK) | BIAS;
    uint32_t q1 = ((w >>  4) & MASK) | BIAS;
    uint32_t q2 = ((w >>  8) & MASK) | BIAS;
    uint32_t q3 = ((w >> 12) & MASK) | BIAS;
    __half2 off1024 = *reinterpret_cast<const __half2*>(&BIAS);
    __half2 h0 = __hsub2(*reinterpret_cast<__half2*>(&q0), off1024);
    __half2 h1 = __hsub2(*reinterpret_cast<__half2*>(&q1), off1024);
    __half2 h2 = __hsub2(*reinterpret_cast<__half2*>(&q2), off1024);
    __half2 h3 = __hsub2(*reinterpret_cast<__half2*>(&q3), off1024);
    uint32_t b0 = *reinterpret_cast<uint32_t*>(&h0);
    uint32_t b1 = *reinterpret_cast<uint32_t*>(&h1);
    uint32_t b2 = *reinterpret_cast<uint32_t*>(&h2);
    uint32_t b3 = *reinterpret_cast<uint32_t*>(&h3);
    r[0] = __byte_perm(b0, b1, 0x5410);  // k0 k1
    r[1] = __byte_perm(b2, b3, 0x5410);  // k2 k3
    r[2] = __byte_perm(b0, b1, 0x7632);  // k4 k5
    r[3] = __byte_perm(b2, b3, 0x7632);  // k6 k7
}

// ---------------- prep: round x to fp16 + group sums of rounded x ----------------
__global__ void prep_kernel(const float* __restrict__ x) {
    int gwarp = (blockIdx.x * blockDim.x + threadIdx.x) >> 5;
    int lane  = threadIdx.x & 31;
    if (gwarp >= M_DIM * NG_DIM) return;
    int m = gwarp / NG_DIM;
    int g = gwarp % NG_DIM;
    size_t base = (size_t)m * K_DIM + (size_t)g * 128;
    const float* xr = x + base;
    float sum = 0.f;
#pragma unroll
    for (int j = 0; j < 4; j++) {
        float v = xr[lane + 32 * j];
        __half hi = __float2half_rn(v);
        g_xhi[base + lane + 32 * j] = hi;
        sum += __half2float(hi);     // S consistent with MMA operand
    }
#pragma unroll
    for (int o = 16; o > 0; o >>= 1) sum += __shfl_xor_sync(0xFFFFFFFFu, sum, o);
    if (lane == 0) g_S[g * M_DIM + m] = sum;
}

// ---------------- pipeline pieces ----------------
// async fill of A plane + packed W + scale/zero rows for group g into buffer sbuf
__device__ __forceinline__ void fill_group_async(
    uint32_t sbuf, int g, int m0, int n0, const int* __restrict__ Wq,
    const float* __restrict__ scales, const float* __restrict__ zeros, int tid) {
    // A: 128 rows x 256B, swizzled
#pragma unroll
    for (int i = 0; i < 4; i++) {
        int idx = tid + i * NTHREADS;           // 0..2047 : 16B chunks
        int row = idx >> 4;
        int c   = idx & 15;
        uint32_t so = (uint32_t)row * 256u + (uint32_t)((c ^ (row & 7)) << 4);
        size_t goff = (size_t)(m0 + row) * K_DIM + (size_t)g * 128 + (size_t)c * 8;
        CP_ASYNC16(sbuf + B_A + so, (const char*)(g_xhi + goff));
    }
    // packed W: 16 kp-rows x 512B, linear
    {
        int kp = tid >> 5;
        int cw = tid & 31;
        CP_ASYNC16(sbuf + B_W + (uint32_t)tid * 16,
                   (const char*)(Wq + (size_t)(g * 16 + kp) * N_DIM + n0 + cw * 4));
    }
    // scales / zeros (128 floats each)
    if (tid < 64) {
        const float* src;
        uint32_t dst;
        if (tid < 32) { src = scales + (size_t)g * N_DIM + n0 + tid * 4;        dst = sbuf + B_SZ + tid * 16; }
        else          { src = zeros  + (size_t)g * N_DIM + n0 + (tid - 32) * 4; dst = sbuf + B_SZ + 512 + (tid - 32) * 16; }
        CP_ASYNC16(dst, src);
    }
}

// dequantize smem-staged packed W into swizzled fp16 B tile (same buffer)
__device__ __forceinline__ void dequant_sts(char* smem, uint32_t bufoff, int tid) {
    const uint32_t* wsm = (const uint32_t*)(smem + bufoff + B_W);
#pragma unroll
    for (int i = 0; i < 4; i++) {
        int idx = tid + i * NTHREADS;           // 0..2047 words
        uint32_t w = wsm[idx];
        uint32_t r[4];
        dequant8(w, r);
        int kp = idx >> 7;                      // 16B k-chunk
        int n  = idx & 127;                     // n within tile
        uint32_t so = (uint32_t)n * 256u + (uint32_t)((kp ^ (n & 7)) << 4);
        *(uint4*)(smem + bufoff + B_B + so) = make_uint4(r[0], r[1], r[2], r[3]);
    }
}

// ---------------- main GEMM: 16 warps (4x4), warp tile 32m x 32n, double-buffered ----------------
__global__ void __launch_bounds__(NTHREADS, 1)
gemm_kernel(const int* __restrict__ Wq, const float* __restrict__ scales,
            const float* __restrict__ zeros, float* __restrict__ out) {
    extern __shared__ char smem[];
    uint32_t sb = smem_u32(smem);
    int tid  = threadIdx.x;
    int wid  = tid >> 5;          // 0..15
    int lane = tid & 31;
    int wm   = wid >> 2;          // 0..3 -> 32 m-rows
    int wn   = wid & 3;           // 0..3 -> 32 n-cols

    int n0 = blockIdx.x * TILE_N;
    int m0 = blockIdx.y * TILE_M;

    float acc[2][4][4];
    float O[2][4][4];
#pragma unroll
    for (int tm = 0; tm < 2; tm++)
#pragma unroll
        for (int tn = 0; tn < 4; tn++)
#pragma unroll
            for (int c = 0; c < 4; c++) { acc[tm][tn][c] = 0.f; O[tm][tn][c] = 0.f; }

    // ldmatrix lane addressing (buffer-relative offsets)
    int rowA = wm * 32 + (lane & 15);
    int sA   = rowA & 7;
    int hA   = lane >> 4;
    uint32_t offA[2] = { (uint32_t)rowA * 256u, (uint32_t)(rowA + 16) * 256u };

    int sB = lane & 7;
    int hB = (lane >> 3) & 1;
    uint32_t offB[2];
#pragma unroll
    for (int j = 0; j < 2; j++) {
        int rowB = wn * 32 + j * 16 + ((lane >> 4) << 3) + (lane & 7);
        offB[j] = (uint32_t)rowB * 256u;
    }

    // ---------------- prologue: stage group 0 ----------------
    fill_group_async(sb + 0, 0, m0, n0, Wq, scales, zeros, tid);
    CP_COMMIT();
    CP_WAIT0();
    __syncthreads();
    dequant_sts(smem, 0, tid);
    __syncthreads();

    for (int g = 0; g < NG_DIM; g++) {
        uint32_t curoff = (uint32_t)(g & 1) * BUF_STRIDE;
        uint32_t nxtoff = curoff ^ BUF_STRIDE;
        bool more = (g + 1 < NG_DIM);

        // stage next group's raw data (A + packed W + sz) while computing
        if (more) {
            fill_group_async(sb + nxtoff, g + 1, m0, n0, Wq, scales, zeros, tid);
            CP_COMMIT();
        }

        // group sums for epilogue
        float Sv[4];
        {
            const float* Sg = g_S + (size_t)g * M_DIM + m0 + wm * 32 + (lane >> 2);
            Sv[0] = Sg[0]; Sv[1] = Sg[8]; Sv[2] = Sg[16]; Sv[3] = Sg[24];
        }

        uint32_t aBs = sb + curoff + B_A;
        uint32_t bBs = sb + curoff + B_B;

        // ---- compute: 8 k16 steps ----
#pragma unroll
        for (int k16 = 0; k16 < 8; k16++) {
            uint32_t b[8];
            uint32_t cB = (uint32_t)(((2 * k16 + hB) ^ sB) << 4);
            LDSM_X4(b[0], b[1], b[2], b[3], bBs + offB[0] + cB);
            LDSM_X4(b[4], b[5], b[6], b[7], bBs + offB[1] + cB);
            uint32_t cA = (uint32_t)(((2 * k16 + hA) ^ sA) << 4);
#pragma unroll
            for (int tm = 0; tm < 2; tm++) {
                uint32_t a[4];
                LDSM_X4(a[0], a[1], a[2], a[3], aBs + offA[tm] + cA);
                MMA16816(acc[tm][0], a, b[0], b[1]);
                MMA16816(acc[tm][1], a, b[2], b[3]);
                MMA16816(acc[tm][2], a, b[4], b[5]);
                MMA16816(acc[tm][3], a, b[6], b[7]);
            }
        }

        // ---- per-group epilogue: O += s * (P - z*S); reset P ----
        const char* szp = smem + curoff + B_SZ;
#pragma unroll
        for (int tn = 0; tn < 4; tn++) {
            int nl = wn * 32 + tn * 8 + (lane & 3) * 2;
            float2 s2 = *(const float2*)(szp + nl * 4);
            float2 z2 = *(const float2*)(szp + 512 + nl * 4);
#pragma unroll
            for (int tm = 0; tm < 2; tm++)
#pragma unroll
                for (int c = 0; c < 4; c++) {
                    float S = Sv[tm * 2 + (c >> 1)];
                    float s = (c & 1) ? s2.y : s2.x;
                    float z = (c & 1) ? z2.y : z2.x;
                    O[tm][tn][c] = fmaf(s, fmaf(-z, S, acc[tm][tn][c]), O[tm][tn][c]);
                    acc[tm][tn][c] = 0.f;
                }
        }

        // ---- finish staging next buffer ----
        if (more) {
            CP_WAIT0();
            __syncthreads();            // W(next) landed for everyone; compute(cur) done
            dequant_sts(smem, nxtoff, tid);
        }
        __syncthreads();                // B(next) visible / cur buffer reusable
    }

    // ---- store output ----
#pragma unroll
    for (int tm = 0; tm < 2; tm++) {
        int r1 = m0 + wm * 32 + tm * 16 + (lane >> 2);
#pragma unroll
        for (int tn = 0; tn < 4; tn++) {
            int nc = n0 + wn * 32 + tn * 8 + (lane & 3) * 2;
            *(float2*)(out + (size_t)r1 * N_DIM + nc)       = make_float2(O[tm][tn][0], O[tm][tn][1]);
            *(float2*)(out + (size_t)(r1 + 8) * N_DIM + nc) = make_float2(O[tm][tn][2], O[tm][tn][3]);
        }
    }
}

// ---------------- launch ----------------
extern "C" void kernel_launch(void* const* d_in, const int* in_sizes, int n_in,
                              void* d_out, int out_size) {
    const float* x      = (const float*)d_in[0];
    const int*   Wq     = (const int*)d_in[1];
    const float* scales = (const float*)d_in[2];
    const float* zeros  = (const float*)d_in[3];
    float* out = (float*)d_out;

    cudaFuncSetAttribute(gemm_kernel, cudaFuncAttributeMaxDynamicSharedMemorySize, SMEM_BYTES);

    int total_threads = M_DIM * NG_DIM * 32;
    prep_kernel<<<total_threads / 256, 256>>>(x);

    dim3 grid(NT, MT);
    gemm_kernel<<<grid, NTHREADS, SMEM_BYTES>>>(Wq, scales, zeros, out);
}

// round 6
// speedup vs baseline: 1.5617x; 1.5617x over previous
#include <cuda_runtime.h>
#include <cuda_fp16.h>
#include <cstdint>

#define M_DIM 8192
#define K_DIM 4096
#define N_DIM 11008
#define NG_DIM 32

#define TILE_M 128
#define TILE_N 64
#define NT (N_DIM / TILE_N) /* 172 */
#define MT (M_DIM / TILE_M) /* 64 */
#define NTHREADS 256

// ---------------- scratch (static device arrays: allocation-free) ----------------
__device__ __half g_xhi[(size_t)M_DIM * K_DIM];
__device__ float  g_S[NG_DIM * M_DIM];   // S[g*M + m] = sum over group g of fp16-rounded x

// ---------------- smem layout (padded rows: 272B stride, conflict-free LDSM) ----------------
// A double buffer: 2 x (128 rows x 272B) ; B single: 64 rows x 272B
#define ROW_STRIDE 272
#define A_BUF_BYTES (TILE_M * ROW_STRIDE)        /* 34816 */
#define OFF_A0 0
#define OFF_A1 A_BUF_BYTES
#define OFF_B  (2 * A_BUF_BYTES)                 /* 69632 */
#define SMEM_BYTES (OFF_B + TILE_N * ROW_STRIDE) /* 87040 */

// ---------------- helpers ----------------
__device__ __forceinline__ uint32_t smem_u32(const void* p) {
    uint32_t a;
    asm("{ .reg .u64 t; cvta.to.shared.u64 t, %1; cvt.u32.u64 %0, t; }" : "=r"(a) : "l"(p));
    return a;
}

#define CP_ASYNC16(dst, src) \
    asm volatile("cp.async.cg.shared.global [%0], [%1], 16;" :: "r"(dst), "l"(src))
#define CP_COMMIT() asm volatile("cp.async.commit_group;" ::: "memory")
#define CP_WAIT0()  asm volatile("cp.async.wait_group 0;" ::: "memory")

#define LDSM_X4(r0, r1, r2, r3, addr) \
    asm volatile("ldmatrix.sync.aligned.m8n8.x4.shared.b16 {%0,%1,%2,%3}, [%4];" \
                 : "=r"(r0), "=r"(r1), "=r"(r2), "=r"(r3) : "r"(addr))

#define MMA16816(d, a, b0v, b1v) \
    asm volatile("mma.sync.aligned.m16n8k16.row.col.f32.f16.f16.f32 " \
                 "{%0,%1,%2,%3}, {%4,%5,%6,%7}, {%8,%9}, {%0,%1,%2,%3};" \
                 : "+f"((d)[0]), "+f"((d)[1]), "+f"((d)[2]), "+f"((d)[3]) \
                 : "r"((a)[0]), "r"((a)[1]), "r"((a)[2]), "r"((a)[3]), \
                   "r"(b0v), "r"(b1v))

// one packed int32 word -> 8 exact fp16 nibble values, K-ascending, as 4 u32
__device__ __forceinline__ void dequant8(uint32_t w, uint32_t r[4]) {
    const uint32_t MASK = 0x000F000Fu, BIAS = 0x64006400u;
    uint32_t q0 = ((w      ) & MASK) | BIAS;
    uint32_t q1 = ((w >>  4) & MASK) | BIAS;
    uint32_t q2 = ((w >>  8) & MASK) | BIAS;
    uint32_t q3 = ((w >> 12) & MASK) | BIAS;
    __half2 off1024 = *reinterpret_cast<const __half2*>(&BIAS);
    __half2 h0 = __hsub2(*reinterpret_cast<__half2*>(&q0), off1024);
    __half2 h1 = __hsub2(*reinterpret_cast<__half2*>(&q1), off1024);
    __half2 h2 = __hsub2(*reinterpret_cast<__half2*>(&q2), off1024);
    __half2 h3 = __hsub2(*reinterpret_cast<__half2*>(&q3), off1024);
    uint32_t b0 = *reinterpret_cast<uint32_t*>(&h0);
    uint32_t b1 = *reinterpret_cast<uint32_t*>(&h1);
    uint32_t b2 = *reinterpret_cast<uint32_t*>(&h2);
    uint32_t b3 = *reinterpret_cast<uint32_t*>(&h3);
    r[0] = __byte_perm(b0, b1, 0x5410);  // k0 k1
    r[1] = __byte_perm(b2, b3, 0x5410);  // k2 k3
    r[2] = __byte_perm(b0, b1, 0x7632);  // k4 k5
    r[3] = __byte_perm(b2, b3, 0x7632);  // k6 k7
}

// ---------------- prep: round x to fp16 + group sums of rounded x ----------------
__global__ void prep_kernel(const float* __restrict__ x) {
    int gwarp = (blockIdx.x * blockDim.x + threadIdx.x) >> 5;
    int lane  = threadIdx.x & 31;
    if (gwarp >= M_DIM * NG_DIM) return;
    int m = gwarp / NG_DIM;
    int g = gwarp % NG_DIM;
    size_t base = (size_t)m * K_DIM + (size_t)g * 128;
    const float* xr = x + base;
    float sum = 0.f;
#pragma unroll
    for (int j = 0; j < 4; j++) {
        float v = xr[lane + 32 * j];
        __half hi = __float2half_rn(v);
        g_xhi[base + lane + 32 * j] = hi;
        sum += __half2float(hi);     // S consistent with MMA operand
    }
#pragma unroll
    for (int o = 16; o > 0; o >>= 1) sum += __shfl_xor_sync(0xFFFFFFFFu, sum, o);
    if (lane == 0) g_S[g * M_DIM + m] = sum;
}

// ---------------- pipeline pieces ----------------
// cp.async A tile for group g into A buffer (128 rows x 256B data, 272B stride)
__device__ __forceinline__ void cp_a(uint32_t abuf, int g, int m0, int tid) {
#pragma unroll
    for (int i = 0; i < 8; i++) {
        int idx = tid + i * NTHREADS;           // 0..2047 16B chunks
        int row = idx >> 4;
        int c   = idx & 15;
        size_t goff = (size_t)(m0 + row) * K_DIM + (size_t)g * 128 + (size_t)c * 8;
        CP_ASYNC16(abuf + (uint32_t)row * ROW_STRIDE + (uint32_t)c * 16,
                   (const char*)(g_xhi + goff));
    }
}

// W packed for this CTA's 64 n-cols, group g: 16 kp x 64 n = 1024 words, 4/thread
__device__ __forceinline__ void ldg_w(uint32_t wv[4], const int* __restrict__ Wq,
                                      int g, int n0, int tid) {
#pragma unroll
    for (int i = 0; i < 4; i++) {
        int idx = tid + i * NTHREADS;
        int kp  = idx >> 6;
        int n   = idx & 63;
        wv[i] = (uint32_t)Wq[(size_t)(g * 16 + kp) * N_DIM + n0 + n];
    }
}

// dequant W regs -> B tile (64 rows x 272B)
__device__ __forceinline__ void sts_b(char* smem, const uint32_t wv[4], int tid) {
#pragma unroll
    for (int i = 0; i < 4; i++) {
        int idx = tid + i * NTHREADS;
        int kp  = idx >> 6;
        int n   = idx & 63;
        uint32_t r[4];
        dequant8(wv[i], r);
        *(uint4*)(smem + OFF_B + (uint32_t)n * ROW_STRIDE + (uint32_t)kp * 16)
            = make_uint4(r[0], r[1], r[2], r[3]);
    }
}

// ---------------- main GEMM: 8 warps (4m x 2n), warp tile 32m x 32n, 2 CTAs/SM ----------------
__global__ void __launch_bounds__(NTHREADS, 2)
gemm_kernel(const int* __restrict__ Wq, const float* __restrict__ scales,
            const float* __restrict__ zeros, float* __restrict__ out) {
    extern __shared__ char smem[];
    uint32_t sb = smem_u32(smem);
    int tid  = threadIdx.x;
    int wid  = tid >> 5;          // 0..7
    int lane = tid & 31;
    int wm   = wid >> 1;          // 0..3 -> 32 m-rows
    int wn   = wid & 1;           // 0..1 -> 32 n-cols

    int n0 = blockIdx.x * TILE_N;
    int m0 = blockIdx.y * TILE_M;

    float acc[2][4][4];
    float O[2][4][4];
#pragma unroll
    for (int tm = 0; tm < 2; tm++)
#pragma unroll
        for (int tn = 0; tn < 4; tn++)
#pragma unroll
            for (int c = 0; c < 4; c++) { acc[tm][tn][c] = 0.f; O[tm][tn][c] = 0.f; }

    // ldmatrix lane addressing (272B padded rows: conflict-free)
    int rowA = wm * 32 + (lane & 15);
    uint32_t offA[2] = {
        (uint32_t)rowA * ROW_STRIDE + (uint32_t)(lane >> 4) * 16,
        (uint32_t)(rowA + 16) * ROW_STRIDE + (uint32_t)(lane >> 4) * 16
    };
    uint32_t offB[2];
#pragma unroll
    for (int j = 0; j < 2; j++) {
        int rowB = wn * 32 + j * 16 + ((lane >> 4) << 3) + (lane & 7);
        offB[j] = sb + OFF_B + (uint32_t)rowB * ROW_STRIDE + (uint32_t)((lane >> 3) & 1) * 16;
    }

    // epilogue gather indices
    int ep_n = wn * 32 + (lane & 3) * 2;         // +tn*8
    const float* srow;
    const float* zrow;

    // ---------------- prologue: stage group 0 ----------------
    uint32_t wv[4];
    cp_a(sb + OFF_A0, 0, m0, tid);
    CP_COMMIT();
    ldg_w(wv, Wq, 0, n0, tid);
    sts_b(smem, wv, tid);
    CP_WAIT0();
    __syncthreads();

    for (int g = 0; g < NG_DIM; g++) {
        uint32_t aBs = sb + ((g & 1) ? OFF_A1 : OFF_A0);
        bool more = (g + 1 < NG_DIM);

        // stage next group: A via cp.async, W into regs; prefetch this group's s/z/S
        if (more) {
            cp_a(sb + ((g & 1) ? OFF_A0 : OFF_A1), g + 1, m0, tid);
            CP_COMMIT();
            ldg_w(wv, Wq, g + 1, n0, tid);
        }
        srow = scales + (size_t)g * N_DIM + n0;
        zrow = zeros + (size_t)g * N_DIM + n0;
        float2 s2[4], z2[4];
#pragma unroll
        for (int tn = 0; tn < 4; tn++) {
            s2[tn] = *(const float2*)(srow + ep_n + tn * 8);
            z2[tn] = *(const float2*)(zrow + ep_n + tn * 8);
        }
        float Sv[4];
        {
            const float* Sg = g_S + (size_t)g * M_DIM + m0 + wm * 32 + (lane >> 2);
            Sv[0] = Sg[0]; Sv[1] = Sg[8]; Sv[2] = Sg[16]; Sv[3] = Sg[24];
        }

        // ---- compute: 8 k16 steps ----
#pragma unroll
        for (int k16 = 0; k16 < 8; k16++) {
            uint32_t ko = (uint32_t)k16 * 32;
            uint32_t b[8];
            LDSM_X4(b[0], b[1], b[2], b[3], offB[0] + ko);
            LDSM_X4(b[4], b[5], b[6], b[7], offB[1] + ko);
#pragma unroll
            for (int tm = 0; tm < 2; tm++) {
                uint32_t a[4];
                LDSM_X4(a[0], a[1], a[2], a[3], aBs + offA[tm] + ko);
                MMA16816(acc[tm][0], a, b[0], b[1]);
                MMA16816(acc[tm][1], a, b[2], b[3]);
                MMA16816(acc[tm][2], a, b[4], b[5]);
                MMA16816(acc[tm][3], a, b[6], b[7]);
            }
        }

        // ---- per-group epilogue: O += s * (P - z*S); reset P ----
#pragma unroll
        for (int tn = 0; tn < 4; tn++) {
#pragma unroll
            for (int tm = 0; tm < 2; tm++)
#pragma unroll
                for (int c = 0; c < 4; c++) {
                    float S = Sv[tm * 2 + (c >> 1)];
                    float s = (c & 1) ? s2[tn].y : s2[tn].x;
                    float z = (c & 1) ? z2[tn].y : z2[tn].x;
                    O[tm][tn][c] = fmaf(s, fmaf(-z, S, acc[tm][tn][c]), O[tm][tn][c]);
                    acc[tm][tn][c] = 0.f;
                }
        }

        // ---- rotate: B consumed -> overwrite with next group's W; wait for A ----
        __syncthreads();
        if (more) {
            sts_b(smem, wv, tid);
            CP_WAIT0();
        }
        __syncthreads();
    }

    // ---- store output ----
#pragma unroll
    for (int tm = 0; tm < 2; tm++) {
        int r1 = m0 + wm * 32 + tm * 16 + (lane >> 2);
#pragma unroll
        for (int tn = 0; tn < 4; tn++) {
            int nc = n0 + wn * 32 + tn * 8 + (lane & 3) * 2;
            *(float2*)(out + (size_t)r1 * N_DIM + nc)       = make_float2(O[tm][tn][0], O[tm][tn][1]);
            *(float2*)(out + (size_t)(r1 + 8) * N_DIM + nc) = make_float2(O[tm][tn][2], O[tm][tn][3]);
        }
    }
}

// ---------------- launch ----------------
extern "C" void kernel_launch(void* const* d_in, const int* in_sizes, int n_in,
                              void* d_out, int out_size) {
    const float* x      = (const float*)d_in[0];
    const int*   Wq     = (const int*)d_in[1];
    const float* scales = (const float*)d_in[2];
    const float* zeros  = (const float*)d_in[3];
    float* out = (float*)d_out;

    cudaFuncSetAttribute(gemm_kernel, cudaFuncAttributeMaxDynamicSharedMemorySize, SMEM_BYTES);

    int total_threads = M_DIM * NG_DIM * 32;
    prep_kernel<<<total_threads / 256, 256>>>(x);

    dim3 grid(NT, MT);
    gemm_kernel<<<grid, NTHREADS, SMEM_BYTES>>>(Wq, scales, zeros, out);
}

// round 7
// speedup vs baseline: 1.5652x; 1.0022x over previous
#include <cuda_runtime.h>
#include <cuda_fp16.h>
#include <cstdint>

#define M_DIM 8192
#define K_DIM 4096
#define N_DIM 11008
#define NG_DIM 32
#define KSTR 4160                 /* K + 64 ext columns, halves per g_A row */

#define TILE_M 128
#define TILE_N 64
#define NT (N_DIM / TILE_N) /* 172 */
#define MT (M_DIM / TILE_M) /* 64 */
#define NTHREADS 256

// ---------------- scratch (static device arrays: allocation-free) ----------------
__device__ __half g_A[(size_t)M_DIM * KSTR];      // x rounded to fp16 + 64 ext cols (S hi/lo)
__device__ float  g_S[NG_DIM * M_DIM];            // group sums of rounded x
__device__ __half g_sf[(size_t)NG_DIM * N_DIM];   // fp16(scales)
__device__ __half g_zsT[(size_t)N_DIM * 32];      // fp16(-z*s), transposed [n][g]

// ---------------- smem layout (padded rows: 272B stride, conflict-free LDSM) ----------------
#define ROW_STRIDE 272
#define A_BUF_BYTES (TILE_M * ROW_STRIDE)        /* 34816 */
#define OFF_A0 0
#define OFF_A1 A_BUF_BYTES
#define OFF_B  (2 * A_BUF_BYTES)                 /* 69632 */
#define OFF_S  (OFF_B + TILE_N * ROW_STRIDE)     /* 87040: two 128B s-row slots */
#define SMEM_BYTES (OFF_S + 256)

// ---------------- helpers ----------------
__device__ __forceinline__ uint32_t smem_u32(const void* p) {
    uint32_t a;
    asm("{ .reg .u64 t; cvta.to.shared.u64 t, %1; cvt.u32.u64 %0, t; }" : "=r"(a) : "l"(p));
    return a;
}

#define CP_ASYNC16(dst, src) \
    asm volatile("cp.async.cg.shared.global [%0], [%1], 16;" :: "r"(dst), "l"(src))
#define CP_COMMIT() asm volatile("cp.async.commit_group;" ::: "memory")
#define CP_WAIT0()  asm volatile("cp.async.wait_group 0;" ::: "memory")

#define LDSM_X4(r0, r1, r2, r3, addr) \
    asm volatile("ldmatrix.sync.aligned.m8n8.x4.shared.b16 {%0,%1,%2,%3}, [%4];" \
                 : "=r"(r0), "=r"(r1), "=r"(r2), "=r"(r3) : "r"(addr))

#define MMA16816(d, a, b0v, b1v) \
    asm volatile("mma.sync.aligned.m16n8k16.row.col.f32.f16.f16.f32 " \
                 "{%0,%1,%2,%3}, {%4,%5,%6,%7}, {%8,%9}, {%0,%1,%2,%3};" \
                 : "+f"((d)[0]), "+f"((d)[1]), "+f"((d)[2]), "+f"((d)[3]) \
                 : "r"((a)[0]), "r"((a)[1]), "r"((a)[2]), "r"((a)[3]), \
                   "r"(b0v), "r"(b1v))

// one packed int32 word -> 8 exact fp16 nibble values, K-ascending, as 4 u32
__device__ __forceinline__ void dequant8(uint32_t w, uint32_t r[4]) {
    const uint32_t MASK = 0x000F000Fu, BIAS = 0x64006400u;
    uint32_t q0 = ((w      ) & MASK) | BIAS;
    uint32_t q1 = ((w >>  4) & MASK) | BIAS;
    uint32_t q2 = ((w >>  8) & MASK) | BIAS;
    uint32_t q3 = ((w >> 12) & MASK) | BIAS;
    __half2 off1024 = *reinterpret_cast<const __half2*>(&BIAS);
    __half2 h0 = __hsub2(*reinterpret_cast<__half2*>(&q0), off1024);
    __half2 h1 = __hsub2(*reinterpret_cast<__half2*>(&q1), off1024);
    __half2 h2 = __hsub2(*reinterpret_cast<__half2*>(&q2), off1024);
    __half2 h3 = __hsub2(*reinterpret_cast<__half2*>(&q3), off1024);
    uint32_t b0 = *reinterpret_cast<uint32_t*>(&h0);
    uint32_t b1 = *reinterpret_cast<uint32_t*>(&h1);
    uint32_t b2 = *reinterpret_cast<uint32_t*>(&h2);
    uint32_t b3 = *reinterpret_cast<uint32_t*>(&h3);
    r[0] = __byte_perm(b0, b1, 0x5410);
    r[1] = __byte_perm(b2, b3, 0x5410);
    r[2] = __byte_perm(b0, b1, 0x7632);
    r[3] = __byte_perm(b2, b3, 0x7632);
}

// ---------------- prep 1: round x to fp16 into g_A + group sums ----------------
__global__ void prep_kernel(const float* __restrict__ x) {
    int gwarp = (blockIdx.x * blockDim.x + threadIdx.x) >> 5;
    int lane  = threadIdx.x & 31;
    if (gwarp >= M_DIM * NG_DIM) return;
    int m = gwarp / NG_DIM;
    int g = gwarp % NG_DIM;
    const float* xr = x + (size_t)m * K_DIM + (size_t)g * 128;
    __half* ar = g_A + (size_t)m * KSTR + (size_t)g * 128;
    float sum = 0.f;
#pragma unroll
    for (int j = 0; j < 4; j++) {
        float v = xr[lane + 32 * j];
        __half hi = __float2half_rn(v);
        ar[lane + 32 * j] = hi;
        sum += __half2float(hi);
    }
#pragma unroll
    for (int o = 16; o > 0; o >>= 1) sum += __shfl_xor_sync(0xFFFFFFFFu, sum, o);
    if (lane == 0) g_S[g * M_DIM + m] = sum;
}

// ---------------- prep 2a: A extension cols (S hi/lo) ----------------
__global__ void prep_ext_kernel() {
    int idx = blockIdx.x * blockDim.x + threadIdx.x;
    if (idx >= M_DIM * NG_DIM) return;
    int m = idx >> 5;
    int g = idx & 31;
    float S = g_S[g * M_DIM + m];
    __half hi = __float2half_rn(S);
    __half lo = __float2half_rn(S - __half2float(hi));
    g_A[(size_t)m * KSTR + 4096 + g] = hi;
    g_A[(size_t)m * KSTR + 4128 + g] = lo;
}

// ---------------- prep 2b: fp16 scales + transposed -z*s table ----------------
__global__ void prep_zs_kernel(const float* __restrict__ scales, const float* __restrict__ zeros) {
    int idx = blockIdx.x * blockDim.x + threadIdx.x;
    if (idx >= NG_DIM * N_DIM) return;
    int g = idx / N_DIM;
    int n = idx - g * N_DIM;
    float s = scales[idx];
    float z = zeros[idx];
    g_sf[idx] = __float2half_rn(s);
    g_zsT[(size_t)n * 32 + g] = __float2half_rn(-z * s);
}

// ---------------- pipeline pieces ----------------
__device__ __forceinline__ void cp_a(uint32_t abuf, int g, int m0, int tid) {
#pragma unroll
    for (int i = 0; i < 8; i++) {
        int idx = tid + i * NTHREADS;           // 0..2047 16B chunks
        int row = idx >> 4;
        int c   = idx & 15;
        size_t goff = (size_t)(m0 + row) * KSTR + (size_t)g * 128 + (size_t)c * 8;
        CP_ASYNC16(abuf + (uint32_t)row * ROW_STRIDE + (uint32_t)c * 16,
                   (const char*)(g_A + goff));
    }
}

// A extension tile (128 rows x 64 halves)
__device__ __forceinline__ void cp_a_ext(uint32_t abuf, int m0, int tid) {
#pragma unroll
    for (int i = 0; i < 4; i++) {
        int idx = tid + i * NTHREADS;           // 0..1023
        int row = idx >> 3;
        int c   = idx & 7;
        size_t goff = (size_t)(m0 + row) * KSTR + 4096 + (size_t)c * 8;
        CP_ASYNC16(abuf + (uint32_t)row * ROW_STRIDE + (uint32_t)c * 16,
                   (const char*)(g_A + goff));
    }
}

// s row (64 halves = 128B) for group g into slot
__device__ __forceinline__ void cp_s(uint32_t sbase, int slot, int g, int n0, int tid) {
    if (tid < 8)
        CP_ASYNC16(sbase + OFF_S + (uint32_t)slot * 128 + (uint32_t)tid * 16,
                   (const char*)(g_sf + (size_t)g * N_DIM + n0 + tid * 8));
}

// B extension: row n gets two copies of zsT[n0+n][0..31]
__device__ __forceinline__ void cp_b_ext(uint32_t sbase, int n0, int tid) {
#pragma unroll
    for (int i = 0; i < 2; i++) {
        int a = tid + i * NTHREADS;             // 0..511
        int row  = a >> 3;
        int part = a & 7;                       // 8 x 16B = 128B dest row
        CP_ASYNC16(sbase + OFF_B + (uint32_t)row * ROW_STRIDE + (uint32_t)part * 16,
                   (const char*)(g_zsT + (size_t)(n0 + row) * 32 + (size_t)(part & 3) * 8));
    }
}

__device__ __forceinline__ void ldg_w(uint32_t wv[4], const int* __restrict__ Wq,
                                      int g, int n0, int tid) {
#pragma unroll
    for (int i = 0; i < 4; i++) {
        int idx = tid + i * NTHREADS;
        int kp  = idx >> 6;
        int n   = idx & 63;
        wv[i] = (uint32_t)Wq[(size_t)(g * 16 + kp) * N_DIM + n0 + n];
    }
}

// dequant + scale-fold -> B tile
__device__ __forceinline__ void sts_b(char* smem, const uint32_t wv[4], int slot, int tid) {
    const __half* srow = (const __half*)(smem + OFF_S + slot * 128);
#pragma unroll
    for (int i = 0; i < 4; i++) {
        int idx = tid + i * NTHREADS;
        int kp  = idx >> 6;
        int n   = idx & 63;
        uint32_t r[4];
        dequant8(wv[i], r);
        __half sh = srow[n];
        __half2 sv = __half2half2(sh);
#pragma unroll
        for (int j = 0; j < 4; j++) {
            __half2 hv = __hmul2(*reinterpret_cast<__half2*>(&r[j]), sv);
            r[j] = *reinterpret_cast<uint32_t*>(&hv);
        }
        *(uint4*)(smem + OFF_B + (uint32_t)n * ROW_STRIDE + (uint32_t)kp * 16)
            = make_uint4(r[0], r[1], r[2], r[3]);
    }
}

// ---------------- main GEMM: pure K=4160 GEMM, no epilogue ----------------
__global__ void __launch_bounds__(NTHREADS, 2)
gemm_kernel(const int* __restrict__ Wq, float* __restrict__ out) {
    extern __shared__ char smem[];
    uint32_t sb = smem_u32(smem);
    int tid  = threadIdx.x;
    int wid  = tid >> 5;          // 0..7
    int lane = tid & 31;
    int wm   = wid >> 1;          // 0..3 -> 32 m-rows
    int wn   = wid & 1;           // 0..1 -> 32 n-cols

    int n0 = blockIdx.x * TILE_N;
    int m0 = blockIdx.y * TILE_M;

    float acc[2][4][4];
#pragma unroll
    for (int tm = 0; tm < 2; tm++)
#pragma unroll
        for (int tn = 0; tn < 4; tn++)
#pragma unroll
            for (int c = 0; c < 4; c++) acc[tm][tn][c] = 0.f;

    // ldmatrix lane addressing (272B padded rows: conflict-free)
    int rowA = wm * 32 + (lane & 15);
    uint32_t offA[2] = {
        (uint32_t)rowA * ROW_STRIDE + (uint32_t)(lane >> 4) * 16,
        (uint32_t)(rowA + 16) * ROW_STRIDE + (uint32_t)(lane >> 4) * 16
    };
    uint32_t offB[2];
#pragma unroll
    for (int j = 0; j < 2; j++) {
        int rowB = wn * 32 + j * 16 + ((lane >> 4) << 3) + (lane & 7);
        offB[j] = sb + OFF_B + (uint32_t)rowB * ROW_STRIDE + (uint32_t)((lane >> 3) & 1) * 16;
    }

    // ---------------- prologue: stage chunk 0 ----------------
    uint32_t wv[4];
    cp_a(sb + OFF_A0, 0, m0, tid);
    cp_s(sb, 0, 0, n0, tid);
    CP_COMMIT();
    ldg_w(wv, Wq, 0, n0, tid);
    CP_WAIT0();
    __syncthreads();              // s row visible
    sts_b(smem, wv, 0, tid);
    __syncthreads();

    for (int g = 0; g < 33; g++) {
        uint32_t aBs = sb + ((g & 1) ? OFF_A1 : OFF_A0);
        uint32_t nxtA = sb + ((g & 1) ? OFF_A0 : OFF_A1);
        int nxt = g + 1;

        // stage next chunk's A (+W regs +s row)
        if (nxt < 32) {
            cp_a(nxtA, nxt, m0, tid);
            cp_s(sb, nxt & 1, nxt, n0, tid);
            CP_COMMIT();
            ldg_w(wv, Wq, nxt, n0, tid);
        } else if (nxt == 32) {
            cp_a_ext(nxtA, m0, tid);
            CP_COMMIT();
        }

        // ---- compute ----
        int nk = (g < 32) ? 8 : 4;
        for (int k16 = 0; k16 < nk; k16++) {
            uint32_t ko = (uint32_t)k16 * 32;
            uint32_t b[8];
            LDSM_X4(b[0], b[1], b[2], b[3], offB[0] + ko);
            LDSM_X4(b[4], b[5], b[6], b[7], offB[1] + ko);
#pragma unroll
            for (int tm = 0; tm < 2; tm++) {
                uint32_t a[4];
                LDSM_X4(a[0], a[1], a[2], a[3], aBs + offA[tm] + ko);
                MMA16816(acc[tm][0], a, b[0], b[1]);
                MMA16816(acc[tm][1], a, b[2], b[3]);
                MMA16816(acc[tm][2], a, b[4], b[5]);
                MMA16816(acc[tm][3], a, b[6], b[7]);
            }
        }

        if (g == 32) break;

        // ---- rotate: B consumed -> refill; wait for next A ----
        __syncthreads();
        if (nxt < 32) {
            sts_b(smem, wv, nxt & 1, tid);
            CP_WAIT0();
        } else {                   // nxt == 32: fill B ext via cp.async
            cp_b_ext(sb, n0, tid);
            CP_COMMIT();
            CP_WAIT0();
        }
        __syncthreads();
    }

    // ---- store output ----
#pragma unroll
    for (int tm = 0; tm < 2; tm++) {
        int r1 = m0 + wm * 32 + tm * 16 + (lane >> 2);
#pragma unroll
        for (int tn = 0; tn < 4; tn++) {
            int nc = n0 + wn * 32 + tn * 8 + (lane & 3) * 2;
            *(float2*)(out + (size_t)r1 * N_DIM + nc)       = make_float2(acc[tm][tn][0], acc[tm][tn][1]);
            *(float2*)(out + (size_t)(r1 + 8) * N_DIM + nc) = make_float2(acc[tm][tn][2], acc[tm][tn][3]);
        }
    }
}

// ---------------- launch ----------------
extern "C" void kernel_launch(void* const* d_in, const int* in_sizes, int n_in,
                              void* d_out, int out_size) {
    const float* x      = (const float*)d_in[0];
    const int*   Wq     = (const int*)d_in[1];
    const float* scales = (const float*)d_in[2];
    const float* zeros  = (const float*)d_in[3];
    float* out = (float*)d_out;

    cudaFuncSetAttribute(gemm_kernel, cudaFuncAttributeMaxDynamicSharedMemorySize, SMEM_BYTES);

    prep_kernel<<<(M_DIM * NG_DIM * 32) / 256, 256>>>(x);
    prep_ext_kernel<<<(M_DIM * NG_DIM) / 256, 256>>>();
    prep_zs_kernel<<<(NG_DIM * N_DIM + 255) / 256, 256>>>(scales, zeros);

    dim3 grid(NT, MT);
    gemm_kernel<<<grid, NTHREADS, SMEM_BYTES>>>(Wq, out);
}

// round 8
// speedup vs baseline: 1.8115x; 1.1574x over previous
#include <cuda_runtime.h>
#include <cuda_fp16.h>
#include <cstdint>

#define M_DIM 8192
#define K_DIM 4096
#define N_DIM 11008
#define NG_DIM 32
#define KSTR 4224                 /* K + 128 ext columns */

#define TILE_M 128
#define TILE_N 128
#define NT (N_DIM / TILE_N) /* 86 */
#define MT (M_DIM / TILE_M) /* 64 */
#define NTHREADS 256

// ---------------- scratch (static device arrays: allocation-free) ----------------
__device__ __half g_A[(size_t)M_DIM * KSTR];      // fp16(x) + 128 ext cols (S hi/hi/lo/lo)
__device__ float  g_S[NG_DIM * M_DIM];            // group sums of rounded x
__device__ __half g_sf[(size_t)NG_DIM * N_DIM];   // fp16(scales)
__device__ __half g_zsT[(size_t)N_DIM * 64];      // [n][0..31]=fp16_hi(-z*s), [32..63]=lo

// ---------------- smem layout (padded rows: 272B stride, conflict-free LDSM) ----------------
#define ROW_STRIDE 272
#define A_BUF_BYTES (TILE_M * ROW_STRIDE)        /* 34816 */
#define OFF_A0 0
#define OFF_A1 A_BUF_BYTES
#define OFF_B  (2 * A_BUF_BYTES)                 /* 69632 */
#define OFF_S  (OFF_B + TILE_N * ROW_STRIDE)     /* 104448: two 256B s-row slots */
#define SMEM_BYTES (OFF_S + 512)                 /* 104960 */

// ---------------- helpers ----------------
__device__ __forceinline__ uint32_t smem_u32(const void* p) {
    uint32_t a;
    asm("{ .reg .u64 t; cvta.to.shared.u64 t, %1; cvt.u32.u64 %0, t; }" : "=r"(a) : "l"(p));
    return a;
}

#define CP_ASYNC16(dst, src) \
    asm volatile("cp.async.cg.shared.global [%0], [%1], 16;" :: "r"(dst), "l"(src))
#define CP_COMMIT() asm volatile("cp.async.commit_group;" ::: "memory")
#define CP_WAIT0()  asm volatile("cp.async.wait_group 0;" ::: "memory")

#define LDSM_X4(r0, r1, r2, r3, addr) \
    asm volatile("ldmatrix.sync.aligned.m8n8.x4.shared.b16 {%0,%1,%2,%3}, [%4];" \
                 : "=r"(r0), "=r"(r1), "=r"(r2), "=r"(r3) : "r"(addr))

#define MMA16816(d, a, b0v, b1v) \
    asm volatile("mma.sync.aligned.m16n8k16.row.col.f32.f16.f16.f32 " \
                 "{%0,%1,%2,%3}, {%4,%5,%6,%7}, {%8,%9}, {%0,%1,%2,%3};" \
                 : "+f"((d)[0]), "+f"((d)[1]), "+f"((d)[2]), "+f"((d)[3]) \
                 : "r"((a)[0]), "r"((a)[1]), "r"((a)[2]), "r"((a)[3]), \
                   "r"(b0v), "r"(b1v))

// one packed int32 word -> 8 exact fp16 nibble values, K-ascending, as 4 u32
__device__ __forceinline__ void dequant8(uint32_t w, uint32_t r[4]) {
    const uint32_t MASK = 0x000F000Fu, BIAS = 0x64006400u;
    uint32_t q0 = ((w      ) & MASK) | BIAS;
    uint32_t q1 = ((w >>  4) & MASK) | BIAS;
    uint32_t q2 = ((w >>  8) & MASK) | BIAS;
    uint32_t q3 = ((w >> 12) & MASK) | BIAS;
    __half2 off1024 = *reinterpret_cast<const __half2*>(&BIAS);
    __half2 h0 = __hsub2(*reinterpret_cast<__half2*>(&q0), off1024);
    __half2 h1 = __hsub2(*reinterpret_cast<__half2*>(&q1), off1024);
    __half2 h2 = __hsub2(*reinterpret_cast<__half2*>(&q2), off1024);
    __half2 h3 = __hsub2(*reinterpret_cast<__half2*>(&q3), off1024);
    uint32_t b0 = *reinterpret_cast<uint32_t*>(&h0);
    uint32_t b1 = *reinterpret_cast<uint32_t*>(&h1);
    uint32_t b2 = *reinterpret_cast<uint32_t*>(&h2);
    uint32_t b3 = *reinterpret_cast<uint32_t*>(&h3);
    r[0] = __byte_perm(b0, b1, 0x5410);
    r[1] = __byte_perm(b2, b3, 0x5410);
    r[2] = __byte_perm(b0, b1, 0x7632);
    r[3] = __byte_perm(b2, b3, 0x7632);
}

// ---------------- prep 1: round x to fp16 into g_A + group sums ----------------
__global__ void prep_kernel(const float* __restrict__ x) {
    int gwarp = (blockIdx.x * blockDim.x + threadIdx.x) >> 5;
    int lane  = threadIdx.x & 31;
    if (gwarp >= M_DIM * NG_DIM) return;
    int m = gwarp / NG_DIM;
    int g = gwarp % NG_DIM;
    const float* xr = x + (size_t)m * K_DIM + (size_t)g * 128;
    __half* ar = g_A + (size_t)m * KSTR + (size_t)g * 128;
    float sum = 0.f;
#pragma unroll
    for (int j = 0; j < 4; j++) {
        float v = xr[lane + 32 * j];
        __half hi = __float2half_rn(v);
        ar[lane + 32 * j] = hi;
        sum += __half2float(hi);
    }
#pragma unroll
    for (int o = 16; o > 0; o >>= 1) sum += __shfl_xor_sync(0xFFFFFFFFu, sum, o);
    if (lane == 0) g_S[g * M_DIM + m] = sum;
}

// ---------------- prep 2a: A extension cols (S hi,hi,lo,lo blocks) ----------------
__global__ void prep_ext_kernel() {
    int idx = blockIdx.x * blockDim.x + threadIdx.x;
    if (idx >= M_DIM * NG_DIM) return;
    int m = idx >> 5;
    int g = idx & 31;
    float S = g_S[g * M_DIM + m];
    __half hi = __float2half_rn(S);
    __half lo = __float2half_rn(S - __half2float(hi));
    __half* ar = g_A + (size_t)m * KSTR + 4096;
    ar[g]      = hi;
    ar[32 + g] = hi;
    ar[64 + g] = lo;
    ar[96 + g] = lo;
}

// ---------------- prep 2b: fp16 scales + transposed -z*s hi/lo table ----------------
__global__ void prep_zs_kernel(const float* __restrict__ scales, const float* __restrict__ zeros) {
    int idx = blockIdx.x * blockDim.x + threadIdx.x;
    if (idx >= NG_DIM * N_DIM) return;
    int g = idx / N_DIM;
    int n = idx - g * N_DIM;
    float s = scales[idx];
    float z = zeros[idx];
    g_sf[idx] = __float2half_rn(s);
    float zs = -z * s;
    __half hi = __float2half_rn(zs);
    __half lo = __float2half_rn(zs - __half2float(hi));
    g_zsT[(size_t)n * 64 + g]      = hi;
    g_zsT[(size_t)n * 64 + 32 + g] = lo;
}

// ---------------- pipeline pieces ----------------
__device__ __forceinline__ void cp_a(uint32_t abuf, int g, int m0, int tid) {
#pragma unroll
    for (int i = 0; i < 8; i++) {
        int idx = tid + i * NTHREADS;           // 0..2047 16B chunks
        int row = idx >> 4;
        int c   = idx & 15;
        size_t goff = (size_t)(m0 + row) * KSTR + (size_t)g * 128 + (size_t)c * 8;
        CP_ASYNC16(abuf + (uint32_t)row * ROW_STRIDE + (uint32_t)c * 16,
                   (const char*)(g_A + goff));
    }
}

// A extension tile (128 rows x 128 halves)
__device__ __forceinline__ void cp_a_ext(uint32_t abuf, int m0, int tid) {
#pragma unroll
    for (int i = 0; i < 4; i++) {
        int idx = tid + i * NTHREADS;           // 0..1023
        int row = idx >> 3;
        int c   = idx & 7;
        size_t goff = (size_t)(m0 + row) * KSTR + 4096 + (size_t)c * 16;
        CP_ASYNC16(abuf + (uint32_t)row * ROW_STRIDE + (uint32_t)c * 32,
                   (const char*)(g_A + goff));
        CP_ASYNC16(abuf + (uint32_t)row * ROW_STRIDE + (uint32_t)c * 32 + 16,
                   (const char*)(g_A + goff + 8));
    }
}

// s row (128 halves = 256B) for group g into slot
__device__ __forceinline__ void cp_s(uint32_t sbase, int slot, int g, int n0, int tid) {
    if (tid < 16)
        CP_ASYNC16(sbase + OFF_S + (uint32_t)slot * 256 + (uint32_t)tid * 16,
                   (const char*)(g_sf + (size_t)g * N_DIM + n0 + tid * 8));
}

// B extension: row n = [zs_hi, zs_lo, zs_hi, zs_lo] 32-col blocks (256B)
__device__ __forceinline__ void cp_b_ext(uint32_t sbase, int n0, int tid) {
#pragma unroll
    for (int i = 0; i < 8; i++) {
        int a = tid + i * NTHREADS;             // 0..2047
        int row  = a >> 4;
        int part = a & 15;                      // 16 x 16B dest row
        uint32_t src_off = (uint32_t)((part >> 2) & 1) * 64 + (uint32_t)(part & 3) * 16;
        CP_ASYNC16(sbase + OFF_B + (uint32_t)row * ROW_STRIDE + (uint32_t)part * 16,
                   (const char*)g_zsT + (size_t)(n0 + row) * 128 + src_off);
    }
}

__device__ __forceinline__ void ldg_w(uint32_t wv[8], const int* __restrict__ Wq,
                                      int g, int n0, int tid) {
#pragma unroll
    for (int i = 0; i < 8; i++) {
        int idx = tid + i * NTHREADS;
        int kp  = idx >> 7;
        int n   = idx & 127;
        wv[i] = (uint32_t)Wq[(size_t)(g * 16 + kp) * N_DIM + n0 + n];
    }
}

// dequant + scale-fold -> B tile (128 rows x 272B)
__device__ __forceinline__ void sts_b(char* smem, const uint32_t wv[8], int slot, int tid) {
    const __half* srow = (const __half*)(smem + OFF_S + slot * 256);
#pragma unroll
    for (int i = 0; i < 8; i++) {
        int idx = tid + i * NTHREADS;
        int kp  = idx >> 7;
        int n   = idx & 127;
        uint32_t r[4];
        dequant8(wv[i], r);
        __half2 sv = __half2half2(srow[n]);
#pragma unroll
        for (int j = 0; j < 4; j++) {
            __half2 hv = __hmul2(*reinterpret_cast<__half2*>(&r[j]), sv);
            r[j] = *reinterpret_cast<uint32_t*>(&hv);
        }
        *(uint4*)(smem + OFF_B + (uint32_t)n * ROW_STRIDE + (uint32_t)kp * 16)
            = make_uint4(r[0], r[1], r[2], r[3]);
    }
}

// ---------------- main GEMM: K=4224 pure GEMM, 8 warps (2m x 4n), warp tile 64x32 ----------------
__global__ void __launch_bounds__(NTHREADS, 2)
gemm_kernel(const int* __restrict__ Wq, float* __restrict__ out) {
    extern __shared__ char smem[];
    uint32_t sb = smem_u32(smem);
    int tid  = threadIdx.x;
    int wid  = tid >> 5;          // 0..7
    int lane = tid & 31;
    int wm   = wid >> 2;          // 0..1 -> 64 m-rows
    int wn   = wid & 3;           // 0..3 -> 32 n-cols

    int n0 = blockIdx.x * TILE_N;
    int m0 = blockIdx.y * TILE_M;

    float acc[4][4][4];           // [tm(16m)][n8][frag]
#pragma unroll
    for (int tm = 0; tm < 4; tm++)
#pragma unroll
        for (int tn = 0; tn < 4; tn++)
#pragma unroll
            for (int c = 0; c < 4; c++) acc[tm][tn][c] = 0.f;

    // ldmatrix lane addressing (272B padded rows: conflict-free)
    uint32_t offA[4];
#pragma unroll
    for (int tm = 0; tm < 4; tm++) {
        int rowA = wm * 64 + tm * 16 + (lane & 15);
        offA[tm] = (uint32_t)rowA * ROW_STRIDE + (uint32_t)(lane >> 4) * 16;
    }
    uint32_t offB[2];
#pragma unroll
    for (int j = 0; j < 2; j++) {
        int rowB = wn * 32 + j * 16 + ((lane >> 4) << 3) + (lane & 7);
        offB[j] = sb + OFF_B + (uint32_t)rowB * ROW_STRIDE + (uint32_t)((lane >> 3) & 1) * 16;
    }

    // ---------------- prologue: stage chunk 0 ----------------
    uint32_t wv[8];
    cp_a(sb + OFF_A0, 0, m0, tid);
    cp_s(sb, 0, 0, n0, tid);
    CP_COMMIT();
    ldg_w(wv, Wq, 0, n0, tid);
    CP_WAIT0();
    __syncthreads();              // s row visible
    sts_b(smem, wv, 0, tid);
    __syncthreads();

    for (int g = 0; g <= 32; g++) {
        uint32_t aBs  = sb + ((g & 1) ? OFF_A1 : OFF_A0);
        uint32_t nxtA = sb + ((g & 1) ? OFF_A0 : OFF_A1);
        int nxt = g + 1;

        // stage next chunk's A (+W regs +s row)
        if (nxt < 32) {
            cp_a(nxtA, nxt, m0, tid);
            cp_s(sb, nxt & 1, nxt, n0, tid);
            CP_COMMIT();
            ldg_w(wv, Wq, nxt, n0, tid);
        } else if (nxt == 32) {
            cp_a_ext(nxtA, m0, tid);
            CP_COMMIT();
        }

        // ---- compute: 8 k16 steps ----
#pragma unroll
        for (int k16 = 0; k16 < 8; k16++) {
            uint32_t ko = (uint32_t)k16 * 32;
            uint32_t b[8];
            LDSM_X4(b[0], b[1], b[2], b[3], offB[0] + ko);
            LDSM_X4(b[4], b[5], b[6], b[7], offB[1] + ko);
#pragma unroll
            for (int tm = 0; tm < 4; tm++) {
                uint32_t a[4];
                LDSM_X4(a[0], a[1], a[2], a[3], aBs + offA[tm] + ko);
                MMA16816(acc[tm][0], a, b[0], b[1]);
                MMA16816(acc[tm][1], a, b[2], b[3]);
                MMA16816(acc[tm][2], a, b[4], b[5]);
                MMA16816(acc[tm][3], a, b[6], b[7]);
            }
        }

        if (g == 32) break;

        // ---- rotate: B consumed -> refill; wait for next A ----
        __syncthreads();
        if (nxt < 32) {
            sts_b(smem, wv, nxt & 1, tid);
            CP_WAIT0();
        } else {                   // nxt == 32: B ext via cp.async
            cp_b_ext(sb, n0, tid);
            CP_COMMIT();
            CP_WAIT0();
        }
        __syncthreads();
    }

    // ---- store output ----
#pragma unroll
    for (int tm = 0; tm < 4; tm++) {
        int r1 = m0 + wm * 64 + tm * 16 + (lane >> 2);
#pragma unroll
        for (int tn = 0; tn < 4; tn++) {
            int nc = n0 + wn * 32 + tn * 8 + (lane & 3) * 2;
            *(float2*)(out + (size_t)r1 * N_DIM + nc)       = make_float2(acc[tm][tn][0], acc[tm][tn][1]);
            *(float2*)(out + (size_t)(r1 + 8) * N_DIM + nc) = make_float2(acc[tm][tn][2], acc[tm][tn][3]);
        }
    }
}

// ---------------- launch ----------------
extern "C" void kernel_launch(void* const* d_in, const int* in_sizes, int n_in,
                              void* d_out, int out_size) {
    const float* x      = (const float*)d_in[0];
    const int*   Wq     = (const int*)d_in[1];
    const float* scales = (const float*)d_in[2];
    const float* zeros  = (const float*)d_in[3];
    float* out = (float*)d_out;

    cudaFuncSetAttribute(gemm_kernel, cudaFuncAttributeMaxDynamicSharedMemorySize, SMEM_BYTES);

    prep_kernel<<<(M_DIM * NG_DIM * 32) / 256, 256>>>(x);
    prep_ext_kernel<<<(M_DIM * NG_DIM) / 256, 256>>>();
    prep_zs_kernel<<<(NG_DIM * N_DIM + 255) / 256, 256>>>(scales, zeros);

    dim3 grid(NT, MT);
    gemm_kernel<<<grid, NTHREADS, SMEM_BYTES>>>(Wq, out);
}